// round 3
// baseline (speedup 1.0000x reference)
#include <cuda_runtime.h>
#include <cuda_bf16.h>

// PyrDown: q = conv5x5(x*m)/conv5x5(m) (reflect pad, den==0->1), then
// jax.image.resize bilinear ANTIALIASED 2x downsample:
//   separable 4-tap [1,3,3,1]/8 over blur cols/rows {2i-1..2i+2},
//   edges renormalized: i==0 -> (3,3,1)/7 on taps 0..2;
//                       i==511 -> (1,3,3)/7 on taps 1021..1023.

#define W 1024
#define H 1024
#define OW 512
#define OH 512
#define TILE_OX 32
#define TILE_OY 16
#define IN_W  (2 * TILE_OX + 6)   // 70 input cols
#define IN_H  (2 * TILE_OY + 6)   // 38 input rows
#define IN_WP 72                  // padded smem row stride
#define BWQ   (2 * TILE_OX + 2)   // 66 blur cols needed
#define BWP   68                  // padded stride for h/q buffers
#define QH    (2 * TILE_OY + 2)   // 34 blur rows needed
#define NTHREADS 256

__device__ __forceinline__ int reflect_idx(int i, int n) {
    if (i < 0) return -i;
    if (i >= n) return 2 * n - 2 - i;
    return i;
}

__global__ __launch_bounds__(NTHREADS)
void pyrdown_kernel(const float* __restrict__ x,
                    const float* __restrict__ m,
                    float* __restrict__ out) {
    __shared__ float sp[IN_H][IN_WP];  // x*m ; later aliased by q
    __shared__ float sm[IN_H][IN_WP];  // m
    __shared__ float hn[IN_H][BWP];    // horizontal conv of x*m
    __shared__ float hd[IN_H][BWP];    // horizontal conv of m

    float (*q)[BWP] = (float (*)[BWP])sp;  // QH x BWP fits in sp (2736 >= 2312)

    const int plane = blockIdx.z;                 // b*C + c, 0..47
    const long pbase = (long)plane * (W * H);
    const int ox0 = blockIdx.x * TILE_OX;
    const int oy0 = blockIdx.y * TILE_OY;
    const int ix0 = 2 * ox0 - 3;                  // input col of smem col 0
    const int iy0 = 2 * oy0 - 3;                  // input row of smem row 0
    const int tid = threadIdx.x;

    // ---- Stage 1: load input halo, p = x*m and m ----
    #pragma unroll 4
    for (int idx = tid; idx < IN_H * IN_W; idx += NTHREADS) {
        const int r = idx / IN_W;
        const int c = idx - r * IN_W;
        const int gy = reflect_idx(iy0 + r, H);
        const int gx = reflect_idx(ix0 + c, W);
        const long g = pbase + (long)gy * W + gx;
        const float xv = __ldg(x + g);
        const float mv = __ldg(m + g);
        sp[r][c] = xv * mv;
        sm[r][c] = mv;
    }
    __syncthreads();

    const float k0 = 1.0f / 16.0f, k1 = 4.0f / 16.0f, k2 = 6.0f / 16.0f;

    // ---- Stage 2: horizontal 5-tap [1,4,6,4,1]/16 (38 x 66) ----
    #pragma unroll 4
    for (int idx = tid; idx < IN_H * BWQ; idx += NTHREADS) {
        const int r = idx / BWQ;
        const int c = idx - r * BWQ;
        hn[r][c] = k0 * (sp[r][c] + sp[r][c + 4])
                 + k1 * (sp[r][c + 1] + sp[r][c + 3])
                 + k2 * sp[r][c + 2];
        hd[r][c] = k0 * (sm[r][c] + sm[r][c + 4])
                 + k1 * (sm[r][c + 1] + sm[r][c + 3])
                 + k2 * sm[r][c + 2];
    }
    __syncthreads();   // stage 3 overwrites sp via q; stage 2 reads must drain

    // ---- Stage 3: vertical 5-tap + masked divide -> q (34 x 66) ----
    #pragma unroll 4
    for (int idx = tid; idx < QH * BWQ; idx += NTHREADS) {
        const int r = idx / BWQ;
        const int c = idx - r * BWQ;
        float num = k0 * (hn[r][c] + hn[r + 4][c])
                  + k1 * (hn[r + 1][c] + hn[r + 3][c])
                  + k2 * hn[r + 2][c];
        float den = k0 * (hd[r][c] + hd[r + 4][c])
                  + k1 * (hd[r + 1][c] + hd[r + 3][c])
                  + k2 * hd[r + 2][c];
        den += (den == 0.0f) ? 1.0f : 0.0f;
        q[r][c] = __fdividef(num, den);
    }
    __syncthreads();

    // ---- Stage 4: antialiased 4x4-tap downsample ----
    // q row r corresponds to blur row (2*oy0 - 1 + r); likewise cols.
    #pragma unroll 2
    for (int idx = tid; idx < TILE_OX * TILE_OY; idx += NTHREADS) {
        const int oyl = idx / TILE_OX;
        const int oxl = idx - oyl * TILE_OX;
        const int ox = ox0 + oxl;
        const int oy = oy0 + oyl;

        float wx0 = 1.0f/8.0f, wx1 = 3.0f/8.0f, wx2 = 3.0f/8.0f, wx3 = 1.0f/8.0f;
        if (ox == 0)        { wx0 = 0.0f; wx1 = 3.0f/7.0f; wx2 = 3.0f/7.0f; wx3 = 1.0f/7.0f; }
        else if (ox == OW-1){ wx0 = 1.0f/7.0f; wx1 = 3.0f/7.0f; wx2 = 3.0f/7.0f; wx3 = 0.0f; }
        float wy0 = 1.0f/8.0f, wy1 = 3.0f/8.0f, wy2 = 3.0f/8.0f, wy3 = 1.0f/8.0f;
        if (oy == 0)        { wy0 = 0.0f; wy1 = 3.0f/7.0f; wy2 = 3.0f/7.0f; wy3 = 1.0f/7.0f; }
        else if (oy == OH-1){ wy0 = 1.0f/7.0f; wy1 = 3.0f/7.0f; wy2 = 3.0f/7.0f; wy3 = 0.0f; }

        const int br = 2 * oyl;   // q-local base row
        const int bc = 2 * oxl;   // q-local base col

        float r0 = wx0*q[br+0][bc] + wx1*q[br+0][bc+1] + wx2*q[br+0][bc+2] + wx3*q[br+0][bc+3];
        float r1 = wx0*q[br+1][bc] + wx1*q[br+1][bc+1] + wx2*q[br+1][bc+2] + wx3*q[br+1][bc+3];
        float r2 = wx0*q[br+2][bc] + wx1*q[br+2][bc+1] + wx2*q[br+2][bc+2] + wx3*q[br+2][bc+3];
        float r3 = wx0*q[br+3][bc] + wx1*q[br+3][bc+1] + wx2*q[br+3][bc+2] + wx3*q[br+3][bc+3];

        const long o = (long)plane * (OW * OH) + (long)oy * OW + ox;
        out[o] = wy0 * r0 + wy1 * r1 + wy2 * r2 + wy3 * r3;
    }
}

extern "C" void kernel_launch(void* const* d_in, const int* in_sizes, int n_in,
                              void* d_out, int out_size) {
    const float* x = (const float*)d_in[0];
    const float* m = (const float*)d_in[1];
    float* out = (float*)d_out;
    dim3 grid(OW / TILE_OX, OH / TILE_OY, 48);
    dim3 block(NTHREADS);
    pyrdown_kernel<<<grid, block>>>(x, m, out);
}

// round 7
// speedup vs baseline: 2.0629x; 2.0629x over previous
#include <cuda_runtime.h>
#include <cuda_bf16.h>

// PyrDown: q = conv5x5(x*m)/conv5x5(m) (reflect pad, den==0->1), then
// antialiased bilinear 2x downsample: separable [1,3,3,1]/8 over blur
// rows/cols {2i-1..2i+2}; edge outputs renormalized ((3,3,1)/7, (1,3,3)/7).
//
// Register-streaming: no smem. Each thread owns 2 input columns / 1 output
// column; vertical conv in a 5-row register ring, horizontal halos via warp
// shuffles. Warps overlap by TWO lanes per side (v needs +-1, q needs +-1
// more), so 28 usable output columns per warp (lanes 2..29). Reflect
// indexing makes halo lanes produce exactly the reflect-padded v values
// their neighbors need.

#define W 1024
#define H 1024
#define OW 512
#define OH 512
#define RPT 16      // output rows per thread
#define WARPS_Y 8   // warps per block (each its own row strip)
#define USABLE 28   // usable output cols per warp (lanes 2..29)

__device__ __forceinline__ int reflect_idx(int i, int n) {
    if (i < 0) return -i;
    if (i >= n) return 2 * n - 2 - i;
    return i;
}

__global__ __launch_bounds__(256)
void pyrdown_kernel(const float* __restrict__ xg,
                    const float* __restrict__ mg,
                    float* __restrict__ out) {
    const int lane  = threadIdx.x;
    const int wy    = threadIdx.y;
    const int plane = blockIdx.z;

    const int ox  = blockIdx.x * USABLE + lane - 2;     // output column (may be OOB)
    const int oy0 = (blockIdx.y * WARPS_Y + wy) * RPT;  // first output row
    const bool valid = (lane >= 2) && (lane <= USABLE + 1) && (ox < OW);

    const size_t pbase = (size_t)plane * (W * H);
    const float* __restrict__ xp = xg + pbase;
    const float* __restrict__ mp = mg + pbase;

    // Own 2 input columns (reflect applied once).
    const int c0 = reflect_idx(2 * ox,     W);
    const int c1 = reflect_idx(2 * ox + 1, W);

    // x-direction downsample weights (antialiased bilinear, edge-renormalized)
    float wx0 = 0.125f, wx1 = 0.375f, wx2 = 0.375f, wx3 = 0.125f;
    if (ox == 0)      { wx0 = 0.f;      wx1 = 3.f/7.f; wx2 = 3.f/7.f; wx3 = 1.f/7.f; }
    if (ox == OW - 1) { wx0 = 1.f/7.f;  wx1 = 3.f/7.f; wx2 = 3.f/7.f; wx3 = 0.f; }

    const int br_start = 2 * oy0 - 1;   // first blur row needed
    const float k0 = 1.f/16.f, k1 = 4.f/16.f, k2 = 6.f/16.f;

    // 5-row ring: {p0, p1, m0, m1} where p = x*m
    float4 ring[5];
    #pragma unroll
    for (int i = 0; i < 4; ++i) {
        const int gy = reflect_idx(br_start - 2 + i, H);
        const float* xr = xp + (size_t)gy * W;
        const float* mr = mp + (size_t)gy * W;
        const float m0 = __ldg(mr + c0), m1 = __ldg(mr + c1);
        ring[i] = make_float4(__ldg(xr + c0) * m0, __ldg(xr + c1) * m1, m0, m1);
    }

    float rvr[4];   // rolling x-downsampled blur-row values
    float* orow = out + (size_t)plane * (OW * OH) + ox;

    #pragma unroll
    for (int lb = 0; lb < 2 * RPT + 2; ++lb) {          // 34 blur rows
        // Load input row br+2 into the ring
        {
            const int gy = reflect_idx(br_start + lb + 2, H);
            const float* xr = xp + (size_t)gy * W;
            const float* mr = mp + (size_t)gy * W;
            const float m0 = __ldg(mr + c0), m1 = __ldg(mr + c1);
            ring[(lb + 4) % 5] = make_float4(__ldg(xr + c0) * m0,
                                             __ldg(xr + c1) * m1, m0, m1);
        }
        const float4 r0 = ring[(lb    ) % 5];
        const float4 r1 = ring[(lb + 1) % 5];
        const float4 r2 = ring[(lb + 2) % 5];
        const float4 r3 = ring[(lb + 3) % 5];
        const float4 r4 = ring[(lb + 4) % 5];

        // Vertical 5-tap at own 2 columns, both fields
        const float vn0 = k0*(r0.x + r4.x) + k1*(r1.x + r3.x) + k2*r2.x;
        const float vn1 = k0*(r0.y + r4.y) + k1*(r1.y + r3.y) + k2*r2.y;
        const float vd0 = k0*(r0.z + r4.z) + k1*(r1.z + r3.z) + k2*r2.z;
        const float vd1 = k0*(r0.w + r4.w) + k1*(r1.w + r3.w) + k2*r2.w;

        // Halo exchange with neighbor lanes
        const unsigned FM = 0xffffffffu;
        const float vnL0 = __shfl_up_sync  (FM, vn0, 1);  // v[2ox-2]
        const float vnL1 = __shfl_up_sync  (FM, vn1, 1);  // v[2ox-1]
        const float vnR0 = __shfl_down_sync(FM, vn0, 1);  // v[2ox+2]
        const float vnR1 = __shfl_down_sync(FM, vn1, 1);  // v[2ox+3]
        const float vdL0 = __shfl_up_sync  (FM, vd0, 1);
        const float vdL1 = __shfl_up_sync  (FM, vd1, 1);
        const float vdR0 = __shfl_down_sync(FM, vd0, 1);
        const float vdR1 = __shfl_down_sync(FM, vd1, 1);

        // Horizontal 5-tap at own 2 blur columns
        const float hn0 = k0*(vnL0 + vnR0) + k1*(vnL1 + vn1) + k2*vn0;
        const float hn1 = k0*(vnL1 + vnR1) + k1*(vn0 + vnR0) + k2*vn1;
        float hd0 = k0*(vdL0 + vdR0) + k1*(vdL1 + vd1) + k2*vd0;
        float hd1 = k0*(vdL1 + vdR1) + k1*(vd0 + vdR0) + k2*vd1;
        hd0 += (hd0 == 0.f) ? 1.f : 0.f;
        hd1 += (hd1 == 0.f) ? 1.f : 0.f;
        const float q0 = __fdividef(hn0, hd0);
        const float q1 = __fdividef(hn1, hd1);

        // x-downsample: q at blur cols {2ox-1, 2ox, 2ox+1, 2ox+2}
        const float qL = __shfl_up_sync  (FM, q1, 1);
        const float qR = __shfl_down_sync(FM, q0, 1);
        rvr[lb & 3] = wx0 * qL + wx1 * q0 + wx2 * q1 + wx3 * qR;

        // y-downsample: emit when 4 blur rows for an output row are ready
        if ((lb >= 3) && (lb & 1)) {
            const int oy = oy0 + ((lb - 3) >> 1);
            float a0 = 0.125f, a1 = 0.375f, a2 = 0.375f, a3 = 0.125f;
            if (oy == 0)      { a0 = 0.f;     a1 = 3.f/7.f; a2 = 3.f/7.f; a3 = 1.f/7.f; }
            if (oy == OH - 1) { a0 = 1.f/7.f; a1 = 3.f/7.f; a2 = 3.f/7.f; a3 = 0.f; }
            const float v = a0 * rvr[(lb - 3) & 3] + a1 * rvr[(lb - 2) & 3]
                          + a2 * rvr[(lb - 1) & 3] + a3 * rvr[lb & 3];
            if (valid) orow[(size_t)oy * OW] = v;
        }
    }
}

extern "C" void kernel_launch(void* const* d_in, const int* in_sizes, int n_in,
                              void* d_out, int out_size) {
    const float* x = (const float*)d_in[0];
    const float* m = (const float*)d_in[1];
    float* out = (float*)d_out;
    dim3 block(32, WARPS_Y, 1);                       // 256 threads
    dim3 grid((OW + USABLE - 1) / USABLE,             // 19
              OH / (WARPS_Y * RPT),                   // 4
              48);
    pyrdown_kernel<<<grid, block>>>(x, m, out);
}